// round 1
// baseline (speedup 1.0000x reference)
#include <cuda_runtime.h>
#include <math.h>

#define B_  32
#define N_  2048
#define D_  512
#define L_  512
#define M_  256

// ---- device scratch (no allocs allowed in kernel_launch) ----
__device__ float g_w[L_ * D_];                 // normalized theta_v rows
__device__ float g_s[L_];                      // row sums of w
__device__ float g_T[(size_t)B_ * L_ * N_];    // Xslices transposed: [B][L][N], 128 MB

// ============================================================
// Kernel A: normalize theta_v rows (weight_norm, g=1) + row sums
// ============================================================
__global__ void normalize_kernel(const float* __restrict__ theta) {
    int l = blockIdx.x;
    const float* row = theta + l * D_;
    float ss = 0.f, sm = 0.f;
    for (int d = threadIdx.x; d < D_; d += blockDim.x) {
        float v = row[d];
        ss += v * v;
        sm += v;
    }
    __shared__ float red0[32], red1[32];
    #pragma unroll
    for (int o = 16; o; o >>= 1) {
        ss += __shfl_down_sync(0xFFFFFFFFu, ss, o);
        sm += __shfl_down_sync(0xFFFFFFFFu, sm, o);
    }
    int w = threadIdx.x >> 5, lane = threadIdx.x & 31;
    if (lane == 0) { red0[w] = ss; red1[w] = sm; }
    __syncthreads();
    if (threadIdx.x == 0) {
        float tss = 0.f, tsm = 0.f;
        int nw = blockDim.x >> 5;
        for (int i = 0; i < nw; i++) { tss += red0[i]; tsm += red1[i]; }
        float inv = 1.0f / sqrtf(tss);
        red0[0] = inv;
        g_s[l] = tsm * inv;
    }
    __syncthreads();
    float inv = red0[0];
    for (int d = threadIdx.x; d < D_; d += blockDim.x)
        g_w[l * D_ + d] = row[d] * inv;
}

// ============================================================
// Kernel B: per-batch GEMM  T[b][l][n] = sum_d w[l][d] * X[b][n][d]
// A = w [L,D] row-major (K contiguous), B = X[b] [N,D] row-major (K contiguous)
// 128x128x16 smem tiling, 256 threads, 8x8 per-thread microtile.
// ============================================================
#define BM 128
#define BN 128
#define BK 16
#define TM 8
#define TN 8

__global__ void __launch_bounds__(256, 2) gemm_kernel(const float* __restrict__ X) {
    int b = blockIdx.z;
    int lBase = blockIdx.y * BM;
    int nBase = blockIdx.x * BN;
    const float* A  = g_w;
    const float* Bm = X + (size_t)b * N_ * D_;
    float* C = g_T + (size_t)b * L_ * N_;

    __shared__ float As[BK][BM + 4];
    __shared__ float Bs[BK][BN + 4];

    int tid = threadIdx.x;
    int tm = tid >> 4;          // 0..15
    int tn = tid & 15;          // 0..15

    float acc[TM][TN];
    #pragma unroll
    for (int i = 0; i < TM; i++)
        #pragma unroll
        for (int j = 0; j < TN; j++) acc[i][j] = 0.f;

    float ar[TM], br[TN];

    for (int k0 = 0; k0 < D_; k0 += BK) {
        // load A tile: 128 rows x 16 cols = 512 float4, 2 per thread
        #pragma unroll
        for (int it = 0; it < 2; it++) {
            int f   = tid + it * 256;
            int row = f >> 2;
            int c4  = (f & 3) << 2;
            float4 v = *reinterpret_cast<const float4*>(&A[(lBase + row) * D_ + k0 + c4]);
            As[c4 + 0][row] = v.x; As[c4 + 1][row] = v.y;
            As[c4 + 2][row] = v.z; As[c4 + 3][row] = v.w;
        }
        // load B tile
        #pragma unroll
        for (int it = 0; it < 2; it++) {
            int f   = tid + it * 256;
            int row = f >> 2;
            int c4  = (f & 3) << 2;
            float4 v = *reinterpret_cast<const float4*>(&Bm[(size_t)(nBase + row) * D_ + k0 + c4]);
            Bs[c4 + 0][row] = v.x; Bs[c4 + 1][row] = v.y;
            Bs[c4 + 2][row] = v.z; Bs[c4 + 3][row] = v.w;
        }
        __syncthreads();

        #pragma unroll
        for (int kk = 0; kk < BK; kk++) {
            #pragma unroll
            for (int i = 0; i < TM; i++) ar[i] = As[kk][tm * TM + i];
            #pragma unroll
            for (int j = 0; j < TN; j++) br[j] = Bs[kk][tn * TN + j];
            #pragma unroll
            for (int i = 0; i < TM; i++)
                #pragma unroll
                for (int j = 0; j < TN; j++)
                    acc[i][j] = fmaf(ar[i], br[j], acc[i][j]);
        }
        __syncthreads();
    }

    // write C[l][n], n contiguous -> coalesced float4 stores
    #pragma unroll
    for (int i = 0; i < TM; i++) {
        int l = lBase + tm * TM + i;
        float* dst = &C[(size_t)l * N_ + nBase + tn * TN];
        #pragma unroll
        for (int j = 0; j < TN; j += 4) {
            float4 v = make_float4(acc[i][j], acc[i][j + 1], acc[i][j + 2], acc[i][j + 3]);
            *reinterpret_cast<float4*>(dst + j) = v;
        }
    }
}

// ============================================================
// Kernel C: per-(b,l) bitonic sort of the 2048-slice + interp + emit
// out[b][l*M + m] = v[m]*s[l] - ynew(rind(m)),  rind = m if s>=0 else M-1-m
// ============================================================
__global__ void __launch_bounds__(256) sort_interp_kernel(const float* __restrict__ ref_pts,
                                                          float* __restrict__ out) {
    __shared__ float smv[N_];
    int bl = blockIdx.x;            // b*L + l
    int b  = bl >> 9;
    int l  = bl & (L_ - 1);
    const float* src = g_T + (size_t)bl * N_;
    int tid = threadIdx.x;

    // coalesced load into smem
    for (int i = tid; i < N_ / 4; i += 256) {
        reinterpret_cast<float4*>(smv)[i] = reinterpret_cast<const float4*>(src)[i];
    }
    __syncthreads();

    // bitonic sort, ascending (2048 elements, 1024 pairs/pass, 4 pairs/thread)
    for (int k = 2; k <= N_; k <<= 1) {
        for (int j = k >> 1; j > 0; j >>= 1) {
            #pragma unroll 4
            for (int t = tid; t < N_ / 2; t += 256) {
                int i = 2 * t - (t & (j - 1));   // index with bit j cleared
                int p = i | j;
                bool up = (i & k) == 0;
                float a = smv[i], c = smv[p];
                if ((a > c) == up) { smv[i] = c; smv[p] = a; }
            }
            __syncthreads();
        }
    }

    // interp at the 256 target quantiles + reference alignment + emit
    float s = g_s[l];
    int m = tid;                 // blockDim == M_
    if (m < M_) {
        int rm = (s >= 0.f) ? m : (M_ - 1 - m);
        // idx = clip(searchsorted(xg, xn[rm], 'left') - 1, 0, N-2), closed form:
        int num = (rm + 1) * (N_ + 1);              // (rm+1)*2049
        int cdiv = (num + M_) / (M_ + 1);            // ceil(num/257)
        int idx = cdiv - 2;
        if (idx < 0) idx = 0;
        if (idx > N_ - 2) idx = N_ - 2;

        float invN1 = 1.0f / (float)(N_ + 1);
        float xg0 = (float)(idx + 1) * invN1;
        float xg1 = (float)(idx + 2) * invN1;
        float xn  = (float)(rm + 1) / (float)(M_ + 1);

        float y0 = smv[idx], y1 = smv[idx + 1];
        float slope = (y1 - y0) / (1.1920929e-7f + (xg1 - xg0));
        float ynew = y0 + slope * (xn - xg0);

        float v = ref_pts[m * D_];                   // ref_pts[m][0] == linspace value
        out[(size_t)b * (L_ * M_) + (size_t)l * M_ + m] = v * s - ynew;
    }
}

// ============================================================
// launch
// ============================================================
extern "C" void kernel_launch(void* const* d_in, const int* in_sizes, int n_in,
                              void* d_out, int out_size) {
    const float* X     = (const float*)d_in[0];
    const float* theta = (const float*)d_in[1];
    const float* ref   = (const float*)d_in[2];
    float* out = (float*)d_out;

    normalize_kernel<<<L_, 256>>>(theta);

    dim3 g(N_ / BN, L_ / BM, B_);
    gemm_kernel<<<g, 256>>>(X);

    sort_interp_kernel<<<B_ * L_, 256>>>(ref, out);
}

// round 3
// speedup vs baseline: 1.5625x; 1.5625x over previous
#include <cuda_runtime.h>
#include <math.h>
#include <stdint.h>

#define B_  32
#define N_  2048
#define D_  512
#define L_  512
#define M_  256

// ---- device scratch ----
__device__ float g_w[L_ * D_];                 // normalized theta_v rows
__device__ float g_s[L_];                      // row sums of w
__device__ float g_T[(size_t)B_ * L_ * N_];    // Xslices transposed: [B][L][N]

// ============================================================
// Kernel A: normalize theta_v rows (weight_norm, g=1) + row sums
// ============================================================
__global__ void normalize_kernel(const float* __restrict__ theta) {
    int l = blockIdx.x;
    const float* row = theta + l * D_;
    float ss = 0.f, sm = 0.f;
    for (int d = threadIdx.x; d < D_; d += blockDim.x) {
        float v = row[d];
        ss += v * v;
        sm += v;
    }
    __shared__ float red0[32], red1[32];
    #pragma unroll
    for (int o = 16; o; o >>= 1) {
        ss += __shfl_down_sync(0xFFFFFFFFu, ss, o);
        sm += __shfl_down_sync(0xFFFFFFFFu, sm, o);
    }
    int w = threadIdx.x >> 5, lane = threadIdx.x & 31;
    if (lane == 0) { red0[w] = ss; red1[w] = sm; }
    __syncthreads();
    if (threadIdx.x == 0) {
        float tss = 0.f, tsm = 0.f;
        int nw = blockDim.x >> 5;
        for (int i = 0; i < nw; i++) { tss += red0[i]; tsm += red1[i]; }
        float inv = 1.0f / sqrtf(tss);
        red0[0] = inv;
        g_s[l] = tsm * inv;
    }
    __syncthreads();
    float inv = red0[0];
    for (int d = threadIdx.x; d < D_; d += blockDim.x)
        g_w[l * D_ + d] = row[d] * inv;
}

// ============================================================
// Kernel B: per-batch GEMM with packed fma.rn.f32x2 (FFMA2)
//   T[b][l][n] = sum_d w[l][d] * X[b][n][d]
// 128x128x16 smem tiling, 256 threads, 8x8 per-thread microtile
// accumulated as 8x4 f32x2 pairs.
// ============================================================
#define BM 128
#define BN 128
#define BK 16
#define TM 8
#define TN 8

__global__ void __launch_bounds__(256, 2) gemm_kernel(const float* __restrict__ X) {
    int b = blockIdx.z;
    int lBase = blockIdx.y * BM;
    int nBase = blockIdx.x * BN;
    const float* A  = g_w;
    const float* Bm = X + (size_t)b * N_ * D_;
    float* C = g_T + (size_t)b * L_ * N_;

    __shared__ float As[BK][BM + 4];
    __shared__ float Bs[BK][BN + 4];

    int tid = threadIdx.x;
    int tm = tid >> 4;          // 0..15
    int tn = tid & 15;          // 0..15

    unsigned long long acc[TM][TN / 2];
    #pragma unroll
    for (int i = 0; i < TM; i++)
        #pragma unroll
        for (int q = 0; q < TN / 2; q++) acc[i][q] = 0ull;

    for (int k0 = 0; k0 < D_; k0 += BK) {
        #pragma unroll
        for (int it = 0; it < 2; it++) {
            int f   = tid + it * 256;
            int row = f >> 2;
            int c4  = (f & 3) << 2;
            float4 v = *reinterpret_cast<const float4*>(&A[(lBase + row) * D_ + k0 + c4]);
            As[c4 + 0][row] = v.x; As[c4 + 1][row] = v.y;
            As[c4 + 2][row] = v.z; As[c4 + 3][row] = v.w;
        }
        #pragma unroll
        for (int it = 0; it < 2; it++) {
            int f   = tid + it * 256;
            int row = f >> 2;
            int c4  = (f & 3) << 2;
            float4 v = *reinterpret_cast<const float4*>(&Bm[(size_t)(nBase + row) * D_ + k0 + c4]);
            Bs[c4 + 0][row] = v.x; Bs[c4 + 1][row] = v.y;
            Bs[c4 + 2][row] = v.z; Bs[c4 + 3][row] = v.w;
        }
        __syncthreads();

        #pragma unroll
        for (int kk = 0; kk < BK; kk++) {
            float4 a0 = *reinterpret_cast<const float4*>(&As[kk][tm * TM]);
            float4 a1 = *reinterpret_cast<const float4*>(&As[kk][tm * TM + 4]);
            float av[8] = {a0.x, a0.y, a0.z, a0.w, a1.x, a1.y, a1.z, a1.w};
            unsigned long long bp[4];
            #pragma unroll
            for (int q = 0; q < 4; q++)
                bp[q] = *reinterpret_cast<const unsigned long long*>(&Bs[kk][tn * TN + 2 * q]);
            #pragma unroll
            for (int i = 0; i < TM; i++) {
                unsigned long long ap;
                asm("mov.b64 %0, {%1, %1};" : "=l"(ap) : "f"(av[i]));
                #pragma unroll
                for (int q = 0; q < 4; q++)
                    asm("fma.rn.f32x2 %0, %1, %2, %0;" : "+l"(acc[i][q]) : "l"(ap), "l"(bp[q]));
            }
        }
        __syncthreads();
    }

    // write C[l][n]
    #pragma unroll
    for (int i = 0; i < TM; i++) {
        float r[8];
        #pragma unroll
        for (int q = 0; q < 4; q++)
            asm("mov.b64 {%0, %1}, %2;" : "=f"(r[2 * q]), "=f"(r[2 * q + 1]) : "l"(acc[i][q]));
        int l = lBase + tm * TM + i;
        float* dst = &C[(size_t)l * N_ + nBase + tn * TN];
        *reinterpret_cast<float4*>(dst)     = make_float4(r[0], r[1], r[2], r[3]);
        *reinterpret_cast<float4*>(dst + 4) = make_float4(r[4], r[5], r[6], r[7]);
    }
}

// ============================================================
// Kernel C: register/shfl bitonic sort (2048 = 256 thr x 8 regs)
// + interp + emit
// ============================================================
__device__ __forceinline__ void ce(float& a, float& b, bool up) {
    float mn = fminf(a, b), mx = fmaxf(a, b);
    a = up ? mn : mx;
    b = up ? mx : mn;
}

__global__ void __launch_bounds__(256) sort_interp_kernel(const float* __restrict__ ref_pts,
                                                          float* __restrict__ out) {
    __shared__ float smv[N_];
    int bl = blockIdx.x;            // b*L + l
    int b  = bl >> 9;
    int l  = bl & (L_ - 1);
    const float* src = g_T + (size_t)bl * N_;
    int t = threadIdx.x;

    float v[8];
    {
        float4 u0 = *reinterpret_cast<const float4*>(src + t * 8);
        float4 u1 = *reinterpret_cast<const float4*>(src + t * 8 + 4);
        v[0] = u0.x; v[1] = u0.y; v[2] = u0.z; v[3] = u0.w;
        v[4] = u1.x; v[5] = u1.y; v[6] = u1.z; v[7] = u1.w;
    }

    // ---- presort: stages k=2,4,8 fully in registers ----
    // k=2 (up = ((i&2)==0))
    ce(v[0], v[1], true);  ce(v[2], v[3], false);
    ce(v[4], v[5], true);  ce(v[6], v[7], false);
    // k=4 (up = ((i&4)==0)): j=2 then j=1
    ce(v[0], v[2], true);  ce(v[1], v[3], true);
    ce(v[4], v[6], false); ce(v[5], v[7], false);
    ce(v[0], v[1], true);  ce(v[2], v[3], true);
    ce(v[4], v[5], false); ce(v[6], v[7], false);
    // k=8 (up = ((t&1)==0)): j=4,2,1
    {
        bool up8 = ((t & 1) == 0);
        ce(v[0], v[4], up8); ce(v[1], v[5], up8); ce(v[2], v[6], up8); ce(v[3], v[7], up8);
        ce(v[0], v[2], up8); ce(v[1], v[3], up8); ce(v[4], v[6], up8); ce(v[5], v[7], up8);
        ce(v[0], v[1], up8); ce(v[2], v[3], up8); ce(v[4], v[5], up8); ce(v[6], v[7], up8);
    }

    // ---- stages k=16..2048 (kt = k/8 = 2..256) ----
    #pragma unroll
    for (int kt = 2; kt <= 256; kt <<= 1) {
        bool up = ((t & kt) == 0);
        #pragma unroll
        for (int jt = kt >> 1; jt >= 1; jt >>= 1) {      // j = jt*8
            bool keepmin = (((t & jt) == 0) == up);
            if (jt >= 32) {
                // cross-warp: exchange via smem
                __syncthreads();
                #pragma unroll
                for (int e = 0; e < 8; e++) smv[t * 8 + e] = v[e];
                __syncthreads();
                int p = t ^ jt;
                #pragma unroll
                for (int e = 0; e < 8; e++) {
                    float w = smv[p * 8 + e];
                    v[e] = keepmin ? fminf(v[e], w) : fmaxf(v[e], w);
                }
            } else {
                // within-warp: shfl.xor
                #pragma unroll
                for (int e = 0; e < 8; e++) {
                    float w = __shfl_xor_sync(0xFFFFFFFFu, v[e], jt);
                    v[e] = keepmin ? fminf(v[e], w) : fmaxf(v[e], w);
                }
            }
        }
        // j=4,2,1 in registers (direction uniform across the 8-block for k>=16)
        ce(v[0], v[4], up); ce(v[1], v[5], up); ce(v[2], v[6], up); ce(v[3], v[7], up);
        ce(v[0], v[2], up); ce(v[1], v[3], up); ce(v[4], v[6], up); ce(v[5], v[7], up);
        ce(v[0], v[1], up); ce(v[2], v[3], up); ce(v[4], v[5], up); ce(v[6], v[7], up);
    }

    // publish sorted array for the gather/interp stage
    __syncthreads();
    #pragma unroll
    for (int e = 0; e < 8; e++) smv[t * 8 + e] = v[e];
    __syncthreads();

    // interp at 256 target quantiles + reference alignment + emit
    float s = g_s[l];
    int m = t;
    if (m < M_) {
        int rm = (s >= 0.f) ? m : (M_ - 1 - m);
        int num = (rm + 1) * (N_ + 1);
        int cdiv = (num + M_) / (M_ + 1);
        int idx = cdiv - 2;
        if (idx < 0) idx = 0;
        if (idx > N_ - 2) idx = N_ - 2;

        float invN1 = 1.0f / (float)(N_ + 1);
        float xg0 = (float)(idx + 1) * invN1;
        float xg1 = (float)(idx + 2) * invN1;
        float xn  = (float)(rm + 1) / (float)(M_ + 1);

        float y0 = smv[idx], y1 = smv[idx + 1];
        float slope = (y1 - y0) / (1.1920929e-7f + (xg1 - xg0));
        float ynew = y0 + slope * (xn - xg0);

        float vr = ref_pts[m * D_];
        out[(size_t)b * (L_ * M_) + (size_t)l * M_ + m] = vr * s - ynew;
    }
}

// ============================================================
// launch
// ============================================================
extern "C" void kernel_launch(void* const* d_in, const int* in_sizes, int n_in,
                              void* d_out, int out_size) {
    const float* X     = (const float*)d_in[0];
    const float* theta = (const float*)d_in[1];
    const float* ref   = (const float*)d_in[2];
    float* out = (float*)d_out;

    normalize_kernel<<<L_, 256>>>(theta);

    dim3 g(N_ / BN, L_ / BM, B_);
    gemm_kernel<<<g, 256>>>(X);

    sort_interp_kernel<<<B_ * L_, 256>>>(ref, out);
}

// round 4
// speedup vs baseline: 1.8208x; 1.1653x over previous
#include <cuda_runtime.h>
#include <math.h>
#include <stdint.h>

#define B_  32
#define N_  2048
#define D_  512
#define L_  512
#define M_  256

// ---- device scratch ----
__device__ float g_w[L_ * D_];                 // normalized theta_v rows
__device__ float g_s[L_];                      // row sums of w
__device__ float g_T[(size_t)B_ * L_ * N_];    // Xslices transposed: [B][L][N]

// ============================================================
// Kernel A: normalize theta_v rows (weight_norm, g=1) + row sums
// ============================================================
__global__ void normalize_kernel(const float* __restrict__ theta) {
    int l = blockIdx.x;
    const float* row = theta + l * D_;
    float ss = 0.f, sm = 0.f;
    for (int d = threadIdx.x; d < D_; d += blockDim.x) {
        float v = row[d];
        ss += v * v;
        sm += v;
    }
    __shared__ float red0[32], red1[32];
    #pragma unroll
    for (int o = 16; o; o >>= 1) {
        ss += __shfl_down_sync(0xFFFFFFFFu, ss, o);
        sm += __shfl_down_sync(0xFFFFFFFFu, sm, o);
    }
    int w = threadIdx.x >> 5, lane = threadIdx.x & 31;
    if (lane == 0) { red0[w] = ss; red1[w] = sm; }
    __syncthreads();
    if (threadIdx.x == 0) {
        float tss = 0.f, tsm = 0.f;
        int nw = blockDim.x >> 5;
        for (int i = 0; i < nw; i++) { tss += red0[i]; tsm += red1[i]; }
        float inv = 1.0f / sqrtf(tss);
        red0[0] = inv;
        g_s[l] = tsm * inv;
    }
    __syncthreads();
    float inv = red0[0];
    for (int d = threadIdx.x; d < D_; d += blockDim.x)
        g_w[l * D_ + d] = row[d] * inv;
}

// ============================================================
// Kernel B: per-batch GEMM, FFMA2 (fma.rn.f32x2),
// double-buffered smem, conflict-free strided-TN mapping.
//   T[b][l][n] = sum_d w[l][d] * X[b][n][d]
// BM=BN=128, BK=16, 256 threads.
// thread (tm,tn): rows lBase+tm*8..+7, cols nBase+tn*4..+3 and +64..+67
// ============================================================
#define BM 128
#define BN 128
#define BK 16
#define TM 8

__global__ void __launch_bounds__(256, 2) gemm_kernel(const float* __restrict__ X) {
    __shared__ float As[2][BK][BM + 4];
    __shared__ float Bs[2][BK][BN + 4];

    int b = blockIdx.z;
    int lBase = blockIdx.y * BM;
    int nBase = blockIdx.x * BN;
    const float* A  = g_w;
    const float* Bm = X + (size_t)b * N_ * D_;
    float* C = g_T + (size_t)b * L_ * N_;

    int tid = threadIdx.x;
    int tm = tid >> 4;          // 0..15
    int tn = tid & 15;          // 0..15

    // gmem load geometry: per tile 512 float4, 2 per thread
    int r0 = (tid + 0)   >> 2, c40 = ((tid + 0)   & 3) << 2;
    int r1 = (tid + 256) >> 2, c41 = ((tid + 256) & 3) << 2;

    unsigned long long acc[TM][4];
    #pragma unroll
    for (int i = 0; i < TM; i++)
        #pragma unroll
        for (int q = 0; q < 4; q++) acc[i][q] = 0ull;

    // ---- prologue: chunk 0 direct to smem[0] ----
    {
        float4 va0 = *reinterpret_cast<const float4*>(&A[(lBase + r0) * D_ + c40]);
        float4 va1 = *reinterpret_cast<const float4*>(&A[(lBase + r1) * D_ + c41]);
        float4 vb0 = *reinterpret_cast<const float4*>(&Bm[(size_t)(nBase + r0) * D_ + c40]);
        float4 vb1 = *reinterpret_cast<const float4*>(&Bm[(size_t)(nBase + r1) * D_ + c41]);
        As[0][c40 + 0][r0] = va0.x; As[0][c40 + 1][r0] = va0.y;
        As[0][c40 + 2][r0] = va0.z; As[0][c40 + 3][r0] = va0.w;
        As[0][c41 + 0][r1] = va1.x; As[0][c41 + 1][r1] = va1.y;
        As[0][c41 + 2][r1] = va1.z; As[0][c41 + 3][r1] = va1.w;
        Bs[0][c40 + 0][r0] = vb0.x; Bs[0][c40 + 1][r0] = vb0.y;
        Bs[0][c40 + 2][r0] = vb0.z; Bs[0][c40 + 3][r0] = vb0.w;
        Bs[0][c41 + 0][r1] = vb1.x; Bs[0][c41 + 1][r1] = vb1.y;
        Bs[0][c41 + 2][r1] = vb1.z; Bs[0][c41 + 3][r1] = vb1.w;
    }
    __syncthreads();

    const int NCHUNK = D_ / BK;   // 32
    for (int c = 0; c < NCHUNK; ++c) {
        int cur = c & 1;
        int nxt = cur ^ 1;

        // prefetch chunk c+1 into registers
        float4 va0, va1, vb0, vb1;
        if (c < NCHUNK - 1) {
            int k0 = (c + 1) * BK;
            va0 = *reinterpret_cast<const float4*>(&A[(lBase + r0) * D_ + k0 + c40]);
            va1 = *reinterpret_cast<const float4*>(&A[(lBase + r1) * D_ + k0 + c41]);
            vb0 = *reinterpret_cast<const float4*>(&Bm[(size_t)(nBase + r0) * D_ + k0 + c40]);
            vb1 = *reinterpret_cast<const float4*>(&Bm[(size_t)(nBase + r1) * D_ + k0 + c41]);
        }

        // compute on smem[cur]
        #pragma unroll
        for (int kk = 0; kk < BK; kk++) {
            float4 a0 = *reinterpret_cast<const float4*>(&As[cur][kk][tm * TM]);
            float4 a1 = *reinterpret_cast<const float4*>(&As[cur][kk][tm * TM + 4]);
            float4 b0 = *reinterpret_cast<const float4*>(&Bs[cur][kk][tn * 4]);
            float4 b1 = *reinterpret_cast<const float4*>(&Bs[cur][kk][tn * 4 + 64]);
            unsigned long long bp[4];
            asm("mov.b64 %0, {%1, %2};" : "=l"(bp[0]) : "f"(b0.x), "f"(b0.y));
            asm("mov.b64 %0, {%1, %2};" : "=l"(bp[1]) : "f"(b0.z), "f"(b0.w));
            asm("mov.b64 %0, {%1, %2};" : "=l"(bp[2]) : "f"(b1.x), "f"(b1.y));
            asm("mov.b64 %0, {%1, %2};" : "=l"(bp[3]) : "f"(b1.z), "f"(b1.w));
            float av[8] = {a0.x, a0.y, a0.z, a0.w, a1.x, a1.y, a1.z, a1.w};
            #pragma unroll
            for (int i = 0; i < TM; i++) {
                unsigned long long ap;
                asm("mov.b64 %0, {%1, %1};" : "=l"(ap) : "f"(av[i]));
                #pragma unroll
                for (int q = 0; q < 4; q++)
                    asm("fma.rn.f32x2 %0, %1, %2, %0;" : "+l"(acc[i][q]) : "l"(ap), "l"(bp[q]));
            }
        }

        // store prefetched chunk to smem[nxt]
        if (c < NCHUNK - 1) {
            As[nxt][c40 + 0][r0] = va0.x; As[nxt][c40 + 1][r0] = va0.y;
            As[nxt][c40 + 2][r0] = va0.z; As[nxt][c40 + 3][r0] = va0.w;
            As[nxt][c41 + 0][r1] = va1.x; As[nxt][c41 + 1][r1] = va1.y;
            As[nxt][c41 + 2][r1] = va1.z; As[nxt][c41 + 3][r1] = va1.w;
            Bs[nxt][c40 + 0][r0] = vb0.x; Bs[nxt][c40 + 1][r0] = vb0.y;
            Bs[nxt][c40 + 2][r0] = vb0.z; Bs[nxt][c40 + 3][r0] = vb0.w;
            Bs[nxt][c41 + 0][r1] = vb1.x; Bs[nxt][c41 + 1][r1] = vb1.y;
            Bs[nxt][c41 + 2][r1] = vb1.z; Bs[nxt][c41 + 3][r1] = vb1.w;
            __syncthreads();
        }
    }

    // ---- epilogue ----
    #pragma unroll
    for (int i = 0; i < TM; i++) {
        float r[8];
        #pragma unroll
        for (int q = 0; q < 4; q++)
            asm("mov.b64 {%0, %1}, %2;" : "=f"(r[2 * q]), "=f"(r[2 * q + 1]) : "l"(acc[i][q]));
        int l = lBase + tm * TM + i;
        float* dst = &C[(size_t)l * N_ + nBase + tn * 4];
        *reinterpret_cast<float4*>(dst)      = make_float4(r[0], r[1], r[2], r[3]);
        *reinterpret_cast<float4*>(dst + 64) = make_float4(r[4], r[5], r[6], r[7]);
    }
}

// ============================================================
// Kernel C: register/shfl bitonic sort (2048 = 256 thr x 8 regs)
// ping-pong smem for cross-warp stages, + interp + emit
// ============================================================
__device__ __forceinline__ void ce(float& a, float& b, bool up) {
    float mn = fminf(a, b), mx = fmaxf(a, b);
    a = up ? mn : mx;
    b = up ? mx : mn;
}

__global__ void __launch_bounds__(256) sort_interp_kernel(const float* __restrict__ ref_pts,
                                                          float* __restrict__ out) {
    __shared__ float smv[2][N_];
    int bl = blockIdx.x;            // b*L + l
    int b  = bl >> 9;
    int l  = bl & (L_ - 1);
    const float* src = g_T + (size_t)bl * N_;
    int t = threadIdx.x;

    float v[8];
    {
        float4 u0 = *reinterpret_cast<const float4*>(src + t * 8);
        float4 u1 = *reinterpret_cast<const float4*>(src + t * 8 + 4);
        v[0] = u0.x; v[1] = u0.y; v[2] = u0.z; v[3] = u0.w;
        v[4] = u1.x; v[5] = u1.y; v[6] = u1.z; v[7] = u1.w;
    }

    // ---- presort: stages k=2,4,8 fully in registers ----
    ce(v[0], v[1], true);  ce(v[2], v[3], false);
    ce(v[4], v[5], true);  ce(v[6], v[7], false);
    ce(v[0], v[2], true);  ce(v[1], v[3], true);
    ce(v[4], v[6], false); ce(v[5], v[7], false);
    ce(v[0], v[1], true);  ce(v[2], v[3], true);
    ce(v[4], v[5], false); ce(v[6], v[7], false);
    {
        bool up8 = ((t & 1) == 0);
        ce(v[0], v[4], up8); ce(v[1], v[5], up8); ce(v[2], v[6], up8); ce(v[3], v[7], up8);
        ce(v[0], v[2], up8); ce(v[1], v[3], up8); ce(v[4], v[6], up8); ce(v[5], v[7], up8);
        ce(v[0], v[1], up8); ce(v[2], v[3], up8); ce(v[4], v[5], up8); ce(v[6], v[7], up8);
    }

    int pp = 0;   // ping-pong selector

    // ---- stages k=16..2048 (kt = k/8 = 2..256) ----
    #pragma unroll
    for (int kt = 2; kt <= 256; kt <<= 1) {
        bool up = ((t & kt) == 0);
        #pragma unroll
        for (int jt = kt >> 1; jt >= 1; jt >>= 1) {      // j = jt*8
            bool keepmin = (((t & jt) == 0) == up);
            if (jt >= 32) {
                // cross-warp: exchange via ping-pong smem, ONE barrier
                float* buf = smv[pp];
                *reinterpret_cast<float4*>(buf + t * 8)     = make_float4(v[0], v[1], v[2], v[3]);
                *reinterpret_cast<float4*>(buf + t * 8 + 4) = make_float4(v[4], v[5], v[6], v[7]);
                __syncthreads();
                int p = t ^ jt;
                float4 w0 = *reinterpret_cast<const float4*>(buf + p * 8);
                float4 w1 = *reinterpret_cast<const float4*>(buf + p * 8 + 4);
                float w[8] = {w0.x, w0.y, w0.z, w0.w, w1.x, w1.y, w1.z, w1.w};
                #pragma unroll
                for (int e = 0; e < 8; e++)
                    v[e] = keepmin ? fminf(v[e], w[e]) : fmaxf(v[e], w[e]);
                pp ^= 1;
            } else {
                #pragma unroll
                for (int e = 0; e < 8; e++) {
                    float w = __shfl_xor_sync(0xFFFFFFFFu, v[e], jt);
                    v[e] = keepmin ? fminf(v[e], w) : fmaxf(v[e], w);
                }
            }
        }
        ce(v[0], v[4], up); ce(v[1], v[5], up); ce(v[2], v[6], up); ce(v[3], v[7], up);
        ce(v[0], v[2], up); ce(v[1], v[3], up); ce(v[4], v[6], up); ce(v[5], v[7], up);
        ce(v[0], v[1], up); ce(v[2], v[3], up); ce(v[4], v[5], up); ce(v[6], v[7], up);
    }

    // publish sorted array (need barrier before reuse of smv[pp])
    __syncthreads();
    {
        float* buf = smv[0];
        *reinterpret_cast<float4*>(buf + t * 8)     = make_float4(v[0], v[1], v[2], v[3]);
        *reinterpret_cast<float4*>(buf + t * 8 + 4) = make_float4(v[4], v[5], v[6], v[7]);
    }
    __syncthreads();

    // interp at 256 target quantiles + reference alignment + emit
    float s = g_s[l];
    int m = t;
    if (m < M_) {
        const float* buf = smv[0];
        int rm = (s >= 0.f) ? m : (M_ - 1 - m);
        int num = (rm + 1) * (N_ + 1);
        int cdiv = (num + M_) / (M_ + 1);
        int idx = cdiv - 2;
        if (idx < 0) idx = 0;
        if (idx > N_ - 2) idx = N_ - 2;

        float invN1 = 1.0f / (float)(N_ + 1);
        float xg0 = (float)(idx + 1) * invN1;
        float xg1 = (float)(idx + 2) * invN1;
        float xn  = (float)(rm + 1) / (float)(M_ + 1);

        float y0 = buf[idx], y1 = buf[idx + 1];
        float slope = (y1 - y0) / (1.1920929e-7f + (xg1 - xg0));
        float ynew = y0 + slope * (xn - xg0);

        float vr = ref_pts[m * D_];
        out[(size_t)b * (L_ * M_) + (size_t)l * M_ + m] = vr * s - ynew;
    }
}

// ============================================================
// launch
// ============================================================
extern "C" void kernel_launch(void* const* d_in, const int* in_sizes, int n_in,
                              void* d_out, int out_size) {
    const float* X     = (const float*)d_in[0];
    const float* theta = (const float*)d_in[1];
    const float* ref   = (const float*)d_in[2];
    float* out = (float*)d_out;

    normalize_kernel<<<L_, 256>>>(theta);

    dim3 g(N_ / BN, L_ / BM, B_);
    gemm_kernel<<<g, 256>>>(X);

    sort_interp_kernel<<<B_ * L_, 256>>>(ref, out);
}